// round 15
// baseline (speedup 1.0000x reference)
#include <cuda_runtime.h>

#define BB 16
#define QQ 300
#define SNUM 16
#define HID 256
#define T_TOT 13125
#define W0 100
#define H0 100
#define QP 3
#define S_SCALE_C 0.077f

#define RG 8                     // rows per row-group
#define NRG (BB * QP * SNUM / RG)   // 96 row-groups
#define NOH 4                    // o-splits
#define OGRP (HID / NOH)         // 64 outputs per block
#define NBLK1 (NRG * NOH)        // 384
#define NTHR 256
#define NCQ 16                   // c-chunks per block
#define CPT (HID / NCQ)          // 16 c per thread
#define PSTRIDE 17               // pool padding (ull units)

// pre-activation layer-2 partials: [row 768][oh 4][k 4]
__device__ __align__(16) float g_part[BB * QP * SNUM * NOH * 4];

typedef unsigned long long ull;

__device__ __forceinline__ ull pack2(float lo, float hi) {
    ull r; asm("mov.b64 %0, {%1, %2};" : "=l"(r) : "f"(lo), "f"(hi)); return r;
}
__device__ __forceinline__ void unpack2(ull v, float& lo, float& hi) {
    asm("mov.b64 {%0, %1}, %2;" : "=f"(lo), "=f"(hi) : "l"(v));
}
__device__ __forceinline__ void fma2(ull& d, ull a, ull b) {
    asm("fma.rn.f32x2 %0, %1, %2, %3;" : "=l"(d) : "l"(a), "l"(b), "l"(d));
}
__device__ __forceinline__ ull add2(ull a, ull b) {
    ull r; asm("add.rn.f32x2 %0, %1, %2;" : "=l"(r) : "l"(a), "l"(b)); return r;
}
__device__ __forceinline__ float tanh_fast(float x) {
    float r; asm("tanh.approx.f32 %0, %1;" : "=f"(r) : "f"(x)); return r;
}

__device__ __forceinline__ void poly_xy(const float* __restrict__ c, int s,
                                        float& spx, float& spy) {
    const float t  = (float)s * (1.0f / (float)(SNUM - 1));
    const float t2 = t * t, t3 = t2 * t;
    spx = 2.0f * (c[0] * t3 + c[1] * t2 + c[2] * t + c[3] - 0.5f);
    spy = 2.0f * (c[4] * t3 + c[5] * t2 + c[6] * t + c[7] - 0.5f);
}

// Kernel 1: block = (row-group of 8 rows, o-split of 64 outputs).
// Register-tiled layer 1 (LDG.128 weights, 32 MACs per weight load),
// layer-2 PARTIAL dots (pre-activation) written to g_part.
__global__ __launch_bounds__(NTHR, 2) void sample_mlp_kernel(
        const float* __restrict__ rp,
        const float* __restrict__ mem,
        const float* __restrict__ w1,
        const float* __restrict__ b1,
        const float* __restrict__ w2) {
    const int blk = blockIdx.x;
    const int tid = threadIdx.x;
    const int rg  = blk >> 2;          // row-group 0..95
    const int oh  = blk & 3;           // o-split 0..3

    __shared__ __align__(16) float gs[HID * RG];                  // [c][r] 8KB
    __shared__ __align__(16) ull  pool[RG / 2 * OGRP * PSTRIDE];  // 34.8KB
    __shared__ float h1s[RG * OGRP];                              // 2KB

    // ---- gather: 8 rows x 256 channels, 8 entries per thread ----
    #pragma unroll
    for (int it = 0; it < RG; it++) {
        const int e = it * NTHR + tid;         // 0..2047
        const int c = e & 255;
        const int r = e >> 8;                  // 0..7
        const int row = rg * RG + r;           // b*48 + qp*16 + s
        const int s  = row & 15;
        const int qp = (row >> 4) % QP;
        const int b  = row / (QP * SNUM);

        float gx, gy;
        poly_xy(rp + ((size_t)b * QQ + qp) * 8, s, gx, gy);
        const float x = (gx + 1.0f) * (W0 * 0.5f) - 0.5f;
        const float y = (gy + 1.0f) * (H0 * 0.5f) - 0.5f;
        const float x0f = floorf(x), y0f = floorf(y);
        const int x0 = (int)x0f, y0 = (int)y0f;
        const float wx1 = x - x0f, wx0 = 1.0f - wx1;
        const float wy1 = y - y0f, wy0 = 1.0f - wy1;

        const float* memb = mem + (size_t)b * T_TOT * HID + c;
        float a = 0.0f;
        #pragma unroll
        for (int dy = 0; dy < 2; dy++) {
            const int yi = y0 + dy;
            if (yi < 0 || yi >= H0) continue;
            const float wy = dy ? wy1 : wy0;
            #pragma unroll
            for (int dx = 0; dx < 2; dx++) {
                const int xi = x0 + dx;
                if (xi < 0 || xi >= W0) continue;
                a += wy * (dx ? wx1 : wx0) *
                     __ldg(memb + (size_t)(yi * W0 + xi) * HID);
            }
        }
        gs[c * RG + r] = a;
    }
    __syncthreads();

    // ---- layer 1: thread = (o4, cq); 16 c-iters, LDG.128 weights ----
    {
        const int o4 = tid & 15;               // group of 4 outputs
        const int cq = tid >> 4;               // c-chunk 0..15
        const int obase = oh * OGRP + 4 * o4;  // global output base

        ull acc[4][4];                          // [j: output][rp: row-pair]
        #pragma unroll
        for (int j = 0; j < 4; j++)
            #pragma unroll
            for (int q = 0; q < 4; q++) acc[j][q] = 0;

        const float4* wv = reinterpret_cast<const float4*>(w1 + obase);
        #pragma unroll
        for (int i = 0; i < CPT; i++) {
            const int c = cq * CPT + i;
            const float4 w4 = __ldg(&wv[c * (HID / 4)]);
            const ull wd0 = pack2(w4.x, w4.x);
            const ull wd1 = pack2(w4.y, w4.y);
            const ull wd2 = pack2(w4.z, w4.z);
            const ull wd3 = pack2(w4.w, w4.w);
            const float* g = &gs[c * RG];
            #pragma unroll
            for (int q = 0; q < 4; q++) {
                const ull gp = *reinterpret_cast<const ull*>(g + 2 * q);
                fma2(acc[0][q], gp, wd0);
                fma2(acc[1][q], gp, wd1);
                fma2(acc[2][q], gp, wd2);
                fma2(acc[3][q], gp, wd3);
            }
        }
        // store partials: pool[(rp*64 + o_local)*17 + cq]
        #pragma unroll
        for (int j = 0; j < 4; j++)
            #pragma unroll
            for (int q = 0; q < 4; q++)
                pool[(q * OGRP + 4 * o4 + j) * PSTRIDE + cq] = acc[j][q];
    }
    __syncthreads();

    // ---- combine 16 c-partials + bias + tanh -> h1s[r][o] ----
    {
        const int o  = tid & 63;               // o_local
        const int q  = tid >> 6;               // row-pair 0..3
        const ull* src = &pool[(q * OGRP + o) * PSTRIDE];
        ull s01 = add2(src[0], src[1]);
        ull s23 = add2(src[2], src[3]);
        ull s45 = add2(src[4], src[5]);
        ull s67 = add2(src[6], src[7]);
        ull s89 = add2(src[8], src[9]);
        ull sAB = add2(src[10], src[11]);
        ull sCD = add2(src[12], src[13]);
        ull sEF = add2(src[14], src[15]);
        ull s = add2(add2(add2(s01, s23), add2(s45, s67)),
                     add2(add2(s89, sAB), add2(sCD, sEF)));
        float v0, v1;
        unpack2(s, v0, v1);
        const float bv = __ldg(&b1[oh * OGRP + o]);
        h1s[(2 * q) * OGRP + o]     = tanh_fast(v0 + bv);
        h1s[(2 * q + 1) * OGRP + o] = tanh_fast(v1 + bv);
    }
    __syncthreads();

    // ---- layer-2 partial dots over this block's 64 outputs ----
    {
        const int wid = tid >> 5, lane = tid & 31;   // warp = row
        const float h0 = h1s[wid * OGRP + lane];
        const float h1v = h1s[wid * OGRP + lane + 32];
        const float4* w2v = reinterpret_cast<const float4*>(w2) + oh * OGRP;
        const float4 wA = __ldg(&w2v[lane]);
        const float4 wB = __ldg(&w2v[lane + 32]);
        float a0 = h0 * wA.x + h1v * wB.x;
        float a1 = h0 * wA.y + h1v * wB.y;
        float a2 = h0 * wA.z + h1v * wB.z;
        float a3 = h0 * wA.w + h1v * wB.w;
        #pragma unroll
        for (int o = 16; o > 0; o >>= 1) {
            a0 += __shfl_xor_sync(0xffffffffu, a0, o);
            a1 += __shfl_xor_sync(0xffffffffu, a1, o);
            a2 += __shfl_xor_sync(0xffffffffu, a2, o);
            a3 += __shfl_xor_sync(0xffffffffu, a3, o);
        }
        if (lane == 0) {
            const int row = rg * RG + wid;
            float4 v = make_float4(a0, a1, a2, a3);
            reinterpret_cast<float4*>(g_part)[row * NOH + oh] = v;
        }
    }
}

// Kernel 2: per (b,q,s): cubic, sum the 4 o-split partials, +b2, tanh, scale.
__global__ void out_kernel(const float* __restrict__ rp,
                           const int* __restrict__ rl,
                           const float* __restrict__ b2,
                           float* __restrict__ out) {
    int idx = blockIdx.x * blockDim.x + threadIdx.x;   // b*Q*S + q*S + s
    if (idx >= BB * QQ * SNUM) return;
    int s = idx % SNUM;
    int q = (idx / SNUM) % QQ;
    int b = idx / (SNUM * QQ);

    const float* rpq = rp + ((size_t)b * QQ + q) * 8;
    float t  = (float)s * (1.0f / (float)(SNUM - 1));
    float t2 = t * t, t3 = t2 * t;
    float spx = 2.0f * (rpq[0] * t3 + rpq[1] * t2 + rpq[2] * t + rpq[3] - 0.5f);
    float spy = 2.0f * (rpq[4] * t3 + rpq[5] * t2 + rpq[6] * t + rpq[7] - 0.5f);

    int lvl = rl[b * QQ + q];                           // in {0,1,2}
    const int row = b * (QP * SNUM) + lvl * SNUM + s;
    const float4* p = reinterpret_cast<const float4*>(g_part) + row * NOH;
    const float4 p0 = p[0], p1 = p[1], p2 = p[2], p3 = p[3];
    const float4 bb = *reinterpret_cast<const float4*>(b2);

    float o0 = S_SCALE_C * tanh_fast(p0.x + p1.x + p2.x + p3.x + bb.x);
    float o1 = S_SCALE_C * tanh_fast(p0.y + p1.y + p2.y + p3.y + bb.y);
    float o2 = S_SCALE_C * tanh_fast(p0.z + p1.z + p2.z + p3.z + bb.z);
    float o3 = S_SCALE_C * tanh_fast(p0.w + p1.w + p2.w + p3.w + bb.w);

    float4 v;
    v.x = o0 + spx;
    v.y = o1 + spy;
    v.z = o2 + spx;
    v.w = o3 + spy;
    reinterpret_cast<float4*>(out)[idx] = v;
}

extern "C" void kernel_launch(void* const* d_in, const int* in_sizes, int n_in,
                              void* d_out, int out_size) {
    const float* ref_polys = (const float*)d_in[0];
    const float* memory    = (const float*)d_in[1];
    const float* w1        = (const float*)d_in[2];
    const float* b1        = (const float*)d_in[3];
    const float* w2        = (const float*)d_in[4];
    const float* b2        = (const float*)d_in[5];
    const int*   ref_lvls  = (const int*)d_in[6];
    float* out = (float*)d_out;

    sample_mlp_kernel<<<NBLK1, NTHR>>>(ref_polys, memory, w1, b1, w2);

    int total = BB * QQ * SNUM;
    out_kernel<<<(total + 255) / 256, 256>>>(ref_polys, ref_lvls, b2, out);
}

// round 16
// speedup vs baseline: 1.1685x; 1.1685x over previous
#include <cuda_runtime.h>

#define BB 16
#define QQ 300
#define SNUM 16
#define HID 256
#define T_TOT 13125
#define W0 100
#define H0 100
#define QP 3
#define S_SCALE_C 0.077f

#define RB 6
#define GSTRIDE 8
#define NBLK1 (BB * QP * SNUM / RB)   // 128
#define NTHR 1024
#define NCQ 4                         // c-split
#define CQL (HID / NCQ)               // 64 c per replica
#define NPAIR (RB / 2)                // 3 row-pairs

// scratch: pre-scaled tanh offsets for the 768 distinct (b, q', s) rows
__device__ __align__(16) float g_off[BB * QP * SNUM * 4];

typedef unsigned long long ull;

__device__ __forceinline__ ull pack2(float lo, float hi) {
    ull r; asm("mov.b64 %0, {%1, %2};" : "=l"(r) : "f"(lo), "f"(hi)); return r;
}
__device__ __forceinline__ void unpack2(ull v, float& lo, float& hi) {
    asm("mov.b64 {%0, %1}, %2;" : "=f"(lo), "=f"(hi) : "l"(v));
}
__device__ __forceinline__ void fma2(ull& d, ull a, ull b) {
    asm("fma.rn.f32x2 %0, %1, %2, %3;" : "=l"(d) : "l"(a), "l"(b), "l"(d));
}
__device__ __forceinline__ ull add2(ull a, ull b) {
    ull r; asm("add.rn.f32x2 %0, %1, %2;" : "=l"(r) : "l"(a), "l"(b)); return r;
}
__device__ __forceinline__ float tanh_fast(float x) {
    float r; asm("tanh.approx.f32 %0, %1;" : "=f"(r) : "f"(x)); return r;
}

__device__ __forceinline__ void poly_xy(const float* __restrict__ c, int s,
                                        float& spx, float& spy) {
    const float t  = (float)s * (1.0f / (float)(SNUM - 1));
    const float t2 = t * t, t3 = t2 * t;
    spx = 2.0f * (c[0] * t3 + c[1] * t2 + c[2] * t + c[3] - 0.5f);
    spy = 2.0f * (c[4] * t3 + c[5] * t2 + c[6] * t + c[7] - 0.5f);
}

// Kernel 1: 128 blocks x 1024 threads. 6 rows per block.
// Layer 1: thread = (output o, c-quarter cq); 64-iteration loop, 3 f32x2 accs.
// 32 warps/SM (8 per SMSP) with 32MB total w1 traffic.
__global__ __launch_bounds__(NTHR, 1) void sample_mlp_kernel(
        const float* __restrict__ rp,
        const float* __restrict__ mem,
        const float* __restrict__ w1,
        const float* __restrict__ b1,
        const float* __restrict__ w2,
        const float* __restrict__ b2) {
    const int blk = blockIdx.x;
    const int tid = threadIdx.x;

    __shared__ __align__(16) float gs[HID * GSTRIDE];          // [c][r] 8KB
    __shared__ __align__(16) ull  pool[NPAIR * NCQ * HID];     // [j][cq][o] 24KB
    __shared__ float h1s[RB * HID];                            // [r][o] 6KB

    // ---- gather: 1536 (c,r) entries over 1024 threads ----
    for (int e = tid; e < RB * HID; e += NTHR) {
        const int c = e & 255;
        const int r = e >> 8;                  // 0..5
        const int row = blk * RB + r;          // b*48 + qp*16 + s
        const int s  = row & 15;
        const int qp = (row >> 4) % QP;
        const int b  = row / (QP * SNUM);

        float gx, gy;
        poly_xy(rp + ((size_t)b * QQ + qp) * 8, s, gx, gy);
        const float x = (gx + 1.0f) * (W0 * 0.5f) - 0.5f;
        const float y = (gy + 1.0f) * (H0 * 0.5f) - 0.5f;
        const float x0f = floorf(x), y0f = floorf(y);
        const int x0 = (int)x0f, y0 = (int)y0f;
        const float wx1 = x - x0f, wx0 = 1.0f - wx1;
        const float wy1 = y - y0f, wy0 = 1.0f - wy1;

        const float* memb = mem + (size_t)b * T_TOT * HID + c;
        float a = 0.0f;
        #pragma unroll
        for (int dy = 0; dy < 2; dy++) {
            const int yi = y0 + dy;
            if (yi < 0 || yi >= H0) continue;
            const float wy = dy ? wy1 : wy0;
            #pragma unroll
            for (int dx = 0; dx < 2; dx++) {
                const int xi = x0 + dx;
                if (xi < 0 || xi >= W0) continue;
                a += wy * (dx ? wx1 : wx0) *
                     __ldg(memb + (size_t)(yi * W0 + xi) * HID);
            }
        }
        gs[c * GSTRIDE + r] = a;
    }
    __syncthreads();

    // ---- layer 1: thread = (o = tid&255, cq = tid>>8); 64 c-iters ----
    {
        const int o  = tid & (HID - 1);
        const int cq = tid >> 8;               // 0..3
        ull a0 = 0, a1 = 0, a2 = 0;            // 3 row-pairs
        const float* wc = w1 + (size_t)(cq * CQL) * HID + o;
        const float* gb = &gs[(cq * CQL) * GSTRIDE];
        #pragma unroll 8
        for (int c = 0; c < CQL; c++) {
            const float w = __ldg(wc + (size_t)c * HID);
            const ull wp = pack2(w, w);
            const float* g = gb + c * GSTRIDE;
            fma2(a0, *reinterpret_cast<const ull*>(g + 0), wp);
            fma2(a1, *reinterpret_cast<const ull*>(g + 2), wp);
            fma2(a2, *reinterpret_cast<const ull*>(g + 4), wp);
        }
        // pool[j][cq][o]: warp = consecutive o, same cq -> conflict-free STS.64
        pool[(0 * NCQ + cq) * HID + o] = a0;
        pool[(1 * NCQ + cq) * HID + o] = a1;
        pool[(2 * NCQ + cq) * HID + o] = a2;
    }
    __syncthreads();

    // ---- combine 4 c-partials + bias + tanh -> h1s[r][o] (768 threads) ----
    if (tid < NPAIR * HID) {
        const int o = tid & (HID - 1);
        const int j = tid >> 8;                // row-pair 0..2
        const ull* src = &pool[j * NCQ * HID + o];
        const ull s = add2(add2(src[0 * HID], src[1 * HID]),
                           add2(src[2 * HID], src[3 * HID]));
        float v0, v1;
        unpack2(s, v0, v1);
        const float bv = __ldg(&b1[o]);
        h1s[(2 * j) * HID + o]     = tanh_fast(v0 + bv);
        h1s[(2 * j + 1) * HID + o] = tanh_fast(v1 + bv);
    }
    __syncthreads();

    // ---- layer 2: warps 0..23 = (row, k); 24 dot products ----
    {
        const int wid = tid >> 5, lane = tid & 31;
        if (wid < RB * 4) {
            const int row = wid >> 2, k = wid & 3;
            float a = 0.0f;
            #pragma unroll
            for (int j = lane; j < HID; j += 32)
                a += h1s[row * HID + j] * __ldg(&w2[j * 4 + k]);
            #pragma unroll
            for (int o = 16; o > 0; o >>= 1)
                a += __shfl_xor_sync(0xffffffffu, a, o);
            if (lane == 0)
                g_off[(blk * RB + row) * 4 + k] =
                    S_SCALE_C * tanh_fast(a + __ldg(&b2[k]));
        }
    }
}

// Kernel 2: per (b,q,s) evaluate the cubic, gather scratch offsets by ref_level.
// (R1 version verbatim — every "improvement" regressed it.)
__global__ void out_kernel(const float* __restrict__ rp,
                           const int* __restrict__ rl,
                           float* __restrict__ out) {
    int idx = blockIdx.x * blockDim.x + threadIdx.x;   // b*Q*S + q*S + s
    if (idx >= BB * QQ * SNUM) return;
    int s = idx % SNUM;
    int q = (idx / SNUM) % QQ;
    int b = idx / (SNUM * QQ);

    const float* rpq = rp + ((size_t)b * QQ + q) * 8;
    float t  = (float)s * (1.0f / (float)(SNUM - 1));
    float t2 = t * t, t3 = t2 * t;
    float spx = 2.0f * (rpq[0] * t3 + rpq[1] * t2 + rpq[2] * t + rpq[3] - 0.5f);
    float spy = 2.0f * (rpq[4] * t3 + rpq[5] * t2 + rpq[6] * t + rpq[7] - 0.5f);

    int lvl = rl[b * QQ + q];                           // in {0,1,2}
    const float* off = g_off + (((size_t)b * QP + lvl) * SNUM + s) * 4;
    float4 v;
    v.x = off[0] + spx;
    v.y = off[1] + spy;
    v.z = off[2] + spx;
    v.w = off[3] + spy;
    reinterpret_cast<float4*>(out)[idx] = v;
}

extern "C" void kernel_launch(void* const* d_in, const int* in_sizes, int n_in,
                              void* d_out, int out_size) {
    const float* ref_polys = (const float*)d_in[0];
    const float* memory    = (const float*)d_in[1];
    const float* w1        = (const float*)d_in[2];
    const float* b1        = (const float*)d_in[3];
    const float* w2        = (const float*)d_in[4];
    const float* b2        = (const float*)d_in[5];
    const int*   ref_lvls  = (const int*)d_in[6];
    float* out = (float*)d_out;

    sample_mlp_kernel<<<NBLK1, NTHR>>>(ref_polys, memory, w1, b1, w2, b2);

    int total = BB * QQ * SNUM;
    out_kernel<<<(total + 255) / 256, 256>>>(ref_polys, ref_lvls, out);
}

// round 17
// speedup vs baseline: 1.3208x; 1.1303x over previous
#include <cuda_runtime.h>

#define BB 16
#define QQ 300
#define SNUM 16
#define HID 256
#define T_TOT 13125
#define W0 100
#define H0 100
#define QP 3
#define S_SCALE_C 0.077f

#define RB 6
#define GSTRIDE 8
#define NBLK (BB * SNUM / 2)          // 128 blocks: (b, s-pair)
#define NTHR 1024
#define NCQ 4                         // c-split
#define CQL (HID / NCQ)               // 64 c per replica
#define NPAIR (RB / 2)                // 3 row-pairs (one per level)

typedef unsigned long long ull;

__device__ __forceinline__ ull pack2(float lo, float hi) {
    ull r; asm("mov.b64 %0, {%1, %2};" : "=l"(r) : "f"(lo), "f"(hi)); return r;
}
__device__ __forceinline__ void unpack2(ull v, float& lo, float& hi) {
    asm("mov.b64 {%0, %1}, %2;" : "=f"(lo), "=f"(hi) : "l"(v));
}
__device__ __forceinline__ void fma2(ull& d, ull a, ull b) {
    asm("fma.rn.f32x2 %0, %1, %2, %3;" : "=l"(d) : "l"(a), "l"(b), "l"(d));
}
__device__ __forceinline__ ull add2(ull a, ull b) {
    ull r; asm("add.rn.f32x2 %0, %1, %2;" : "=l"(r) : "l"(a), "l"(b)); return r;
}
__device__ __forceinline__ float tanh_fast(float x) {
    float r; asm("tanh.approx.f32 %0, %1;" : "=f"(r) : "f"(x)); return r;
}

__device__ __forceinline__ void poly_xy(const float* __restrict__ c, int s,
                                        float& spx, float& spy) {
    const float t  = (float)s * (1.0f / (float)(SNUM - 1));
    const float t2 = t * t, t3 = t2 * t;
    spx = 2.0f * (c[0] * t3 + c[1] * t2 + c[2] * t + c[3] - 0.5f);
    spy = 2.0f * (c[4] * t3 + c[5] * t2 + c[6] * t + c[7] - 0.5f);
}

// Single fused kernel, NO global barrier.
// Block = (b, s-pair {s0,s1}) -> owns rows (b, qp=0..2, s in {s0,s1}).
// Since all 3 levels for (b,s) are block-local, the block can write
// out[b,q,s0/s1] for every q directly from its smem offsets.
__global__ __launch_bounds__(NTHR, 1) void fused_kernel(
        const float* __restrict__ rp,
        const float* __restrict__ mem,
        const float* __restrict__ w1,
        const float* __restrict__ b1,
        const float* __restrict__ w2,
        const float* __restrict__ b2,
        const int* __restrict__ rl,
        float* __restrict__ out) {
    const int blk = blockIdx.x;
    const int tid = threadIdx.x;
    const int b   = blk >> 3;              // batch
    const int s0  = (blk & 7) * 2;         // first s of the pair

    __shared__ __align__(16) float gs[HID * GSTRIDE];          // [c][r] 8KB
    __shared__ __align__(16) ull  pool[NPAIR * NCQ * HID];     // [j][cq][o] 24KB
    __shared__ float h1s[RB * HID];                            // [r][o] 6KB
    __shared__ __align__(16) float offs[RB][4];                // scaled offsets

    // ---- phase 1: gather 6 rows (qp 0..2, ss 0..1) x 256 channels ----
    // local row r = qp*2 + ss  (pairs along ss -> f32x2-friendly)
    for (int e = tid; e < RB * HID; e += NTHR) {
        const int c  = e & 255;
        const int r  = e >> 8;             // 0..5
        const int qp = r >> 1;
        const int s  = s0 + (r & 1);

        float gx, gy;
        poly_xy(rp + ((size_t)b * QQ + qp) * 8, s, gx, gy);
        const float x = (gx + 1.0f) * (W0 * 0.5f) - 0.5f;
        const float y = (gy + 1.0f) * (H0 * 0.5f) - 0.5f;
        const float x0f = floorf(x), y0f = floorf(y);
        const int x0 = (int)x0f, y0 = (int)y0f;
        const float wx1 = x - x0f, wx0 = 1.0f - wx1;
        const float wy1 = y - y0f, wy0 = 1.0f - wy1;

        const float* memb = mem + (size_t)b * T_TOT * HID + c;
        float a = 0.0f;
        #pragma unroll
        for (int dy = 0; dy < 2; dy++) {
            const int yi = y0 + dy;
            if (yi < 0 || yi >= H0) continue;
            const float wy = dy ? wy1 : wy0;
            #pragma unroll
            for (int dx = 0; dx < 2; dx++) {
                const int xi = x0 + dx;
                if (xi < 0 || xi >= W0) continue;
                a += wy * (dx ? wx1 : wx0) *
                     __ldg(memb + (size_t)(yi * W0 + xi) * HID);
            }
        }
        gs[c * GSTRIDE + r] = a;
    }
    __syncthreads();

    // ---- phase 2: layer 1, thread = (o, c-quarter), 64 c-iters ----
    {
        const int o  = tid & (HID - 1);
        const int cq = tid >> 8;               // 0..3
        ull a0 = 0, a1 = 0, a2 = 0;            // pairs for qp = 0,1,2
        const float* wc = w1 + (size_t)(cq * CQL) * HID + o;
        const float* gb = &gs[(cq * CQL) * GSTRIDE];
        #pragma unroll 8
        for (int c = 0; c < CQL; c++) {
            const float w = __ldg(wc + (size_t)c * HID);
            const ull wp = pack2(w, w);
            const float* g = gb + c * GSTRIDE;
            fma2(a0, *reinterpret_cast<const ull*>(g + 0), wp);
            fma2(a1, *reinterpret_cast<const ull*>(g + 2), wp);
            fma2(a2, *reinterpret_cast<const ull*>(g + 4), wp);
        }
        pool[(0 * NCQ + cq) * HID + o] = a0;
        pool[(1 * NCQ + cq) * HID + o] = a1;
        pool[(2 * NCQ + cq) * HID + o] = a2;
    }
    __syncthreads();

    // ---- combine 4 c-partials + bias + tanh -> h1s[r][o] ----
    if (tid < NPAIR * HID) {
        const int o = tid & (HID - 1);
        const int j = tid >> 8;                // level qp 0..2
        const ull* src = &pool[j * NCQ * HID + o];
        const ull s = add2(add2(src[0 * HID], src[1 * HID]),
                           add2(src[2 * HID], src[3 * HID]));
        float v0, v1;
        unpack2(s, v0, v1);
        const float bv = __ldg(&b1[o]);
        h1s[(2 * j) * HID + o]     = tanh_fast(v0 + bv);   // ss = 0
        h1s[(2 * j + 1) * HID + o] = tanh_fast(v1 + bv);   // ss = 1
    }
    __syncthreads();

    // ---- phase 3: layer 2, warps 0..23 = (r, k); scaled offsets to smem ----
    {
        const int wid = tid >> 5, lane = tid & 31;
        if (wid < RB * 4) {
            const int r = wid >> 2, k = wid & 3;
            float a = 0.0f;
            #pragma unroll
            for (int j = lane; j < HID; j += 32)
                a += h1s[r * HID + j] * __ldg(&w2[j * 4 + k]);
            #pragma unroll
            for (int o = 16; o > 0; o >>= 1)
                a += __shfl_xor_sync(0xffffffffu, a, o);
            if (lane == 0)
                offs[r][k] = S_SCALE_C * tanh_fast(a + __ldg(&b2[k]));
        }
    }
    __syncthreads();

    // ---- phase 4: write out[b, q, s0/s1] for all q (block-local offsets) ----
    for (int t = tid; t < 2 * QQ; t += NTHR) {
        const int q  = t >> 1;
        const int ss = t & 1;
        const int s  = s0 + ss;
        const int lvl = rl[b * QQ + q];        // 0..2

        float spx, spy;
        poly_xy(rp + ((size_t)b * QQ + q) * 8, s, spx, spy);

        const float* o4 = offs[lvl * 2 + ss];
        float4 v;
        v.x = o4[0] + spx;
        v.y = o4[1] + spy;
        v.z = o4[2] + spx;
        v.w = o4[3] + spy;
        reinterpret_cast<float4*>(out)[((size_t)b * QQ + q) * SNUM + s] = v;
    }
}

extern "C" void kernel_launch(void* const* d_in, const int* in_sizes, int n_in,
                              void* d_out, int out_size) {
    const float* ref_polys = (const float*)d_in[0];
    const float* memory    = (const float*)d_in[1];
    const float* w1        = (const float*)d_in[2];
    const float* b1        = (const float*)d_in[3];
    const float* w2        = (const float*)d_in[4];
    const float* b2        = (const float*)d_in[5];
    const int*   ref_lvls  = (const int*)d_in[6];
    float* out = (float*)d_out;

    fused_kernel<<<NBLK, NTHR>>>(ref_polys, memory, w1, b1, w2, b2, ref_lvls, out);
}